// round 11
// baseline (speedup 1.0000x reference)
#include <cuda_runtime.h>

#define BATCH 4
#define C1    32
#define C2    64
#define MROWS 512
#define NB    256
#define NT    512

// Intermediates (no allocation allowed -> __device__ globals)
__device__ float g_z1[BATCH * C1 * 256];           // conv1 out: [b][ic][16x16]
__device__ __align__(16) float g_V  [MROWS * C2];  // lookup @ Wv  [m][d]
__device__ __align__(16) float g_LT4[C2 * MROWS];  // lookup as float4 [k/4][m][4]
__device__ __align__(16) float g_w2T4[512 * C2];   // conv2 w as float4 [k/4][oc][4]
__device__ unsigned g_bar;                         // monotonic grid-barrier ticket

// Software grid barrier: valid because all NB blocks are co-resident:
// __launch_bounds__(512, 2) caps regs at 64 -> 2 blocks/SM (65536 regs = RF),
// smem ~13KB/block -> 26KB/SM; 256 blocks <= 148*2 = 296 capacity.
// Monotonic counter -> safe across graph replays with no reset.
__device__ __forceinline__ void gridbar() {
    __threadfence();
    __syncthreads();
    if (threadIdx.x == 0) {
        unsigned ticket = atomicAdd(&g_bar, 1u);
        unsigned target = (ticket / NB + 1u) * NB;
        while (*(volatile unsigned*)&g_bar < target) { }
        __threadfence();
    }
    __syncthreads();
}

__global__ void __launch_bounds__(NT, 2) fused_kernel(
    const float* __restrict__ x,  const float* __restrict__ w1, const float* __restrict__ b1,
    const float* __restrict__ w2, const float* __restrict__ b2,
    const float* __restrict__ lookup, const float* __restrict__ Wv,
    const float* __restrict__ Wo, float* __restrict__ out)
{
    __shared__ __align__(16) float sm[3264];    // 13 KB, phase-overlaid
    float* st  = sm;            // 64: token vector (persists B -> C)
    // Phase A aliases:
    float* slk = sm + 64;       // 128: this block's 2 lookup rows
    float* sw1 = sm + 192;      // 48:  conv1 weights for this oc
    // Phase B aliases:
    float* z1v = sm + 64;       // 512: conv2 input vector [k]
    float* zp  = sm + 576;      // 512: conv2 partials
    // Phase C aliases:
    float* ss  = sm + 64;       // 512: softmax weights
    float* red = sm + 576;      // 32
    float* part= sm + 608;      // 2048: [32 g][64 d]
    float* pre = sm + 2656;     // 64
    float* pf  = sm + 2720;     // 512

    int t    = threadIdx.x;
    int blk  = blockIdx.x;
    int lane = t & 31, warp = t >> 5;

    // ============ Phase A: 4-way split, uniform & small =====================
    //  t<128    : conv1 for 128 outputs (b=blk>>6, oc=(blk>>1)&31,
    //             pixels (blk&1)*128 + t)
    //  [128,256): LT4 scatter of 2 lookup rows
    //  [256,384): w2T4 scatter of 128 w2 elements
    //  [384,512): V for 2 rows x 64 d
    if (t < 48)                 sw1[t] = w1[((blk >> 1) & 31) * 48 + t];
    if (t >= 128 && t < 256)    slk[t - 128] = lookup[blk * 128 + (t - 128)];
    __syncthreads();

    if (t < 128) {
        int b = blk >> 6, pix = (blk & 1) * 128 + t;
        int oh = pix >> 4, ow = pix & 15;
        int iw0 = ow * 2 - 1;
        float acc = b1[(blk >> 1) & 31];
        #pragma unroll
        for (int ic = 0; ic < 3; ic++) {
            const float* xp  = x + (b * 3 + ic) * 1024;
            const float* swp = sw1 + ic * 16;
            #pragma unroll
            for (int kh = 0; kh < 4; kh++) {
                int ih = oh * 2 - 1 + kh;
                if ((unsigned)ih < 32u) {
                    const float* xr = xp + ih * 32;
                    if (iw0 >= 0)  acc += xr[iw0]     * swp[kh * 4];
                    acc += xr[iw0 + 1] * swp[kh * 4 + 1];
                    acc += xr[iw0 + 2] * swp[kh * 4 + 2];
                    if (iw0 < 29)  acc += xr[iw0 + 3] * swp[kh * 4 + 3];
                }
            }
        }
        g_z1[blk * 128 + t] = fmaxf(acc, 0.0f);   // == (b*32+oc)*256 + pix
    } else if (t < 256) {
        int i = t - 128;                          // 0..127
        int k = i >> 1, mi = i & 1;               // m = 2*blk + mi
        g_LT4[(k >> 2) * 2048 + (blk * 2 + mi) * 4 + (k & 3)] = slk[mi * 64 + k];
    } else if (t < 384) {
        int j = blk * 128 + (t - 256);            // 0..32767, coalesced read
        int k = j & 511, oc = j >> 9;
        g_w2T4[(k >> 2) * 256 + oc * 4 + (k & 3)] = w2[j];
    } else {
        int i = t - 384;                          // 0..127
        int d = i & 63;
        const float* row = slk + (i >> 6) * 64;
        float a0 = 0.f, a1 = 0.f;
        #pragma unroll 8
        for (int k = 0; k < 64; k += 2) {
            a0 += row[k]     * Wv[(k    ) * 64 + d];
            a1 += row[k + 1] * Wv[(k + 1) * 64 + d];
        }
        g_V[(blk * 2 + (i >> 6)) * 64 + d] = a0 + a1;
    }
    gridbar();   // the ONLY global sync

    // ============ Phase B: conv2 for this block's ONE token =================
    int b = blk >> 6, pix = blk & 63;
    {
        int r0 = 2 * (pix >> 3) - 1, c0 = 2 * (pix & 7) - 1;

        // gather conv2 input vector: z1v[k], k = ic*16 + kh*4 + kw; 1 el/thread
        {
            int ic = t >> 4, kh = (t >> 2) & 3, kw = t & 3;
            int ih = r0 + kh, iw = c0 + kw;
            float v = 0.0f;
            if ((unsigned)ih < 16u && (unsigned)iw < 16u)
                v = g_z1[(b * C1 + ic) * 256 + ih * 16 + iw];
            z1v[t] = v;
        }
        __syncthreads();

        // GEMV: thread (oc = t&63, qr = t>>6 in 0..7); 16 LDG.128 weight loads
        {
            int oc = t & 63, qr = t >> 6;
            const float4* wt4 = (const float4*)g_w2T4 + qr * 1024 + oc;
            const float4* zv4 = (const float4*)z1v + qr * 16;
            float a = 0.f, c = 0.f;
            #pragma unroll 8
            for (int k4 = 0; k4 < 16; k4 += 2) {
                float4 w0 = wt4[k4 * 64], w1r = wt4[(k4 + 1) * 64];
                float4 v0 = zv4[k4],      v1r = zv4[k4 + 1];
                a += w0.x * v0.x + w0.y * v0.y + w0.z * v0.z + w0.w * v0.w;
                c += w1r.x * v1r.x + w1r.y * v1r.y + w1r.z * v1r.z + w1r.w * v1r.w;
            }
            zp[t] = a + c;
        }
        __syncthreads();
        if (t < 64) {
            float s = (zp[t] + zp[64 + t]) + (zp[128 + t] + zp[192 + t])
                    + (zp[256 + t] + zp[320 + t]) + (zp[384 + t] + zp[448 + t]);
            st[t] = fmaxf(s + b2[t], 0.0f);
        }
        __syncthreads();
    }

    // ============ Phase C: Hopfield retrieve (1 token) ======================
    // scores for memory row t; 16 LDG.128 of LT4; no max subtraction
    // (scores are O(0.3), exp exact-safe; softmax mathematically unchanged)
    {
        const float4* LT4 = (const float4*)g_LT4;    // [k4][m]
        const float4* st4 = (const float4*)st;
        float a = 0.f, c = 0.f;
        #pragma unroll 8
        for (int k4 = 0; k4 < 16; k4 += 2) {
            float4 L0 = LT4[k4 * 512 + t];
            float4 L1 = LT4[(k4 + 1) * 512 + t];
            float4 u0 = st4[k4], u1 = st4[k4 + 1];
            a += L0.x * u0.x + L0.y * u0.y + L0.z * u0.z + L0.w * u0.w;
            c += L1.x * u1.x + L1.y * u1.y + L1.z * u1.z + L1.w * u1.w;
        }
        ss[t] = __expf((a + c) * 0.125f);     // 1/sqrt(64)
    }

    // block sum
    float u = ss[t];
    #pragma unroll
    for (int o = 16; o; o >>= 1) u += __shfl_xor_sync(0xffffffffu, u, o);
    if (lane == 0) red[warp] = u;
    __syncthreads();                 // covers ss writes + red
    float tot = red[0];
    #pragma unroll
    for (int i = 1; i < 16; i++) tot += red[i];
    float inv = __frcp_rn(tot);

    // p@V: thread (g = t>>4 in 0..31, q = t&15); 16 LDG.128 of V
    {
        int g = t >> 4, q = t & 15;
        const float4* V4 = (const float4*)g_V + g * 256 + q;   // m = g*16..
        const float* pp = ss + g * 16;
        float4 A = make_float4(0.f, 0.f, 0.f, 0.f);
        #pragma unroll 8
        for (int m = 0; m < 16; m++) {
            float4 v = V4[m * 16];
            float p = pp[m];
            A.x += p * v.x; A.y += p * v.y; A.z += p * v.z; A.w += p * v.w;
        }
        *(float4*)(part + g * 64 + q * 4) = A;
    }
    __syncthreads();
    if (t < 64) {
        float s = 0.f;
        #pragma unroll 8
        for (int gg = 0; gg < 32; gg += 2)
            s += part[gg * 64 + t] + part[(gg + 1) * 64 + t];
        pre[t] = s * inv;
    }
    __syncthreads();

    // @Wo: thread (h = t>>6 in 0..7, e = t&63); Wo coalesced
    {
        int e = t & 63, h = t >> 6;
        float acc = 0.f;
        int d0 = h * 8;
        #pragma unroll
        for (int d = d0; d < d0 + 8; d++) acc += pre[d] * Wo[d * 64 + e];
        pf[t] = acc;
    }
    __syncthreads();
    if (t < 64)
        out[b * 4096 + t * 64 + pix] =
            ((pf[t] + pf[t + 64]) + (pf[t + 128] + pf[t + 192]))
          + ((pf[t + 256] + pf[t + 320]) + (pf[t + 384] + pf[t + 448]));
}

// ---------------------------------------------------------------------------
extern "C" void kernel_launch(void* const* d_in, const int* in_sizes, int n_in,
                              void* d_out, int out_size) {
    const float* x       = (const float*)d_in[0];
    const float* conv1_w = (const float*)d_in[1];
    const float* conv1_b = (const float*)d_in[2];
    const float* conv2_w = (const float*)d_in[3];
    const float* conv2_b = (const float*)d_in[4];
    const float* lookup  = (const float*)d_in[5];
    const float* Wv      = (const float*)d_in[6];
    const float* Wo      = (const float*)d_in[7];
    float* out = (float*)d_out;

    fused_kernel<<<NB, NT>>>(x, conv1_w, conv1_b, conv2_w, conv2_b,
                             lookup, Wv, Wo, out);
}

// round 12
// speedup vs baseline: 1.3208x; 1.3208x over previous
#include <cuda_runtime.h>

#define BATCH 4
#define C1    32
#define C2    64
#define MROWS 512
#define NB    128
#define NT    512

// Intermediates (no allocation allowed -> __device__ globals)
__device__ float g_z1[BATCH * C1 * 256];           // conv1 out: [b][ic][16x16]
__device__ __align__(16) float g_V  [MROWS * C2];  // lookup @ Wv  [m][d]
__device__ __align__(16) float g_LT4[C2 * MROWS];  // lookup as float4 [k/4][m][4]
__device__ __align__(16) float g_w2T4[512 * C2];   // conv2 w as float4 [k/4][oc][4]
__device__ unsigned g_bar;                         // monotonic grid-barrier ticket

// Software grid barrier: valid because all NB blocks are co-resident
// (128 blocks <= 148 SMs, 512 thr, 24KB smem). Monotonic counter -> safe
// across graph replays with no reset.
__device__ __forceinline__ void gridbar() {
    __threadfence();
    __syncthreads();
    if (threadIdx.x == 0) {
        unsigned ticket = atomicAdd(&g_bar, 1u);
        unsigned target = (ticket / NB + 1u) * NB;
        while (*(volatile unsigned*)&g_bar < target) { }
        __threadfence();
    }
    __syncthreads();
}

__global__ void __launch_bounds__(NT, 1) fused_kernel(
    const float* __restrict__ x,  const float* __restrict__ w1, const float* __restrict__ b1,
    const float* __restrict__ w2, const float* __restrict__ b2,
    const float* __restrict__ lookup, const float* __restrict__ Wv,
    const float* __restrict__ Wo, float* __restrict__ out)
{
    __shared__ __align__(16) float sm[5920];   // 23.7 KB, phase-overlaid
    float* st  = sm;            // 128: 2 token vectors (persist B -> C)
    // Phase A aliases:
    float* sw1 = sm + 128;      // 48:  conv1 weights for this oc
    float* slk = sm + 192;      // 256: this block's 4 lookup rows
    // Phase B aliases:
    float* z1v = sm + 128;      // 1024: conv2 input vecs [pix][512]
    float* zpA = sm + 1152;     // 512:  conv2 partials pixel0
    float* zpB = sm + 1664;     // 512:  conv2 partials pixel1
    // Phase C aliases:
    float* ss0 = sm + 128;      // 512
    float* ss1 = sm + 640;      // 512
    float* red = sm + 1152;     // 32
    float* part= sm + 1184;     // 4096: [tok][32 g][64 d]
    float* pre = sm + 5280;     // 128
    float* pf  = sm + 5408;     // 512

    int t    = threadIdx.x;
    int blk  = blockIdx.x;
    int lane = t & 31, warp = t >> 5;

    // ============ Phase A: conv1 (t<256) || LT4 + vmat + w2T4 (t>=256) ======
    if (t < 48)   sw1[t] = w1[(blk & 31) * 48 + t];
    if (t >= 256) slk[t - 256] = lookup[blk * 256 + (t - 256)];
    __syncthreads();

    if (t < 256) {
        // conv1: block -> (b, oc); thread -> output pixel. k4 s2 p1 relu.
        int b = blk >> 5, oc = blk & 31;
        int oh = t >> 4, ow = t & 15;
        int iw0 = ow * 2 - 1;
        float acc = b1[oc];
        #pragma unroll
        for (int ic = 0; ic < 3; ic++) {
            const float* xp  = x + (b * 3 + ic) * 1024;
            const float* swp = sw1 + ic * 16;
            #pragma unroll
            for (int kh = 0; kh < 4; kh++) {
                int ih = oh * 2 - 1 + kh;
                if ((unsigned)ih < 32u) {
                    const float* xr = xp + ih * 32;
                    if (iw0 >= 0)  acc += xr[iw0]     * swp[kh * 4];
                    acc += xr[iw0 + 1] * swp[kh * 4 + 1];
                    acc += xr[iw0 + 2] * swp[kh * 4 + 2];
                    if (iw0 < 29)  acc += xr[iw0 + 3] * swp[kh * 4 + 3];
                }
            }
        }
        g_z1[(b * C1 + oc) * 256 + t] = fmaxf(acc, 0.0f);
    } else {
        int i = t - 256;                              // 0..255
        // LT4: element [k>>2][4*blk+mi] component (k&3)
        {
            int k = i >> 2, mi = i & 3;
            g_LT4[(k >> 2) * 2048 + blk * 16 + mi * 4 + (k & 3)] = slk[mi * 64 + k];
        }
        // w2T4: element [k>>2][oc] component (k&3); coalesced read of w2
        {
            int j = blk * 256 + i;                    // 0..32767
            int k = j & 511, oc = j >> 9;
            g_w2T4[(k >> 2) * 256 + oc * 4 + (k & 3)] = w2[j];
        }
        // vmat: V[4blk+r][d] = row_r . Wv[:,d]
        int d = i & 63;
        const float* row = slk + (i >> 6) * 64;
        float a0 = 0.f, a1 = 0.f, a2 = 0.f, a3 = 0.f;
        #pragma unroll
        for (int k = 0; k < 64; k += 4) {
            a0 += row[k]     * Wv[(k    ) * 64 + d];
            a1 += row[k + 1] * Wv[(k + 1) * 64 + d];
            a2 += row[k + 2] * Wv[(k + 2) * 64 + d];
            a3 += row[k + 3] * Wv[(k + 3) * 64 + d];
        }
        g_V[blk * 256 + i] = (a0 + a1) + (a2 + a3);
    }
    gridbar();   // the ONLY global sync

    int b = blk >> 5, p0 = (blk & 31) * 2;    // 2 adjacent pixels, same row

    // ============ Phase B: conv2 (prefetched weights) =======================
    // Prefetch GEMV weights NOW (ready since gridbar); latency hides behind
    // the z1v gather + sync below.
    int oc = t & 63, qr = t >> 6;
    float4 Wreg[16];
    {
        const float4* wt4 = (const float4*)g_w2T4 + qr * 1024 + oc;  // [k4][oc]
        #pragma unroll
        for (int k4 = 0; k4 < 16; k4++) Wreg[k4] = wt4[k4 * 64];
    }

    {
        int r0 = 2 * (p0 >> 3) - 1, c0 = 2 * (p0 & 7) - 1;
        // gather conv2 input vectors: z1v[pix][k], k = ic*16+kh*4+kw
        #pragma unroll
        for (int i = t; i < 1024; i += NT) {
            int pix = i >> 9, k = i & 511;
            int ic = k >> 4, kh = (k >> 2) & 3, kw = k & 3;
            int ih = r0 + kh, iw = c0 + kw + 2 * pix;
            float v = 0.0f;
            if ((unsigned)ih < 16u && (unsigned)iw < 16u)
                v = g_z1[(b * C1 + ic) * 256 + ih * 16 + iw];
            z1v[i] = v;
        }
    }
    __syncthreads();

    // GEMV FMA from registers
    {
        const float4* zv4 = (const float4*)z1v;
        float a = 0.f, c = 0.f;
        #pragma unroll
        for (int k4 = 0; k4 < 16; k4++) {
            float4 w  = Wreg[k4];
            float4 v0 = zv4[qr * 16 + k4];
            float4 v1 = zv4[128 + qr * 16 + k4];
            a += w.x * v0.x + w.y * v0.y + w.z * v0.z + w.w * v0.w;
            c += w.x * v1.x + w.y * v1.y + w.z * v1.z + w.w * v1.w;
        }
        zpA[t] = a;
        zpB[t] = c;
    }

    // Prefetch score-loop LT4 columns NOW; latency hides behind zp sync +
    // st reduce below.
    float4 Lreg[16];
    {
        const float4* LT4 = (const float4*)g_LT4;    // [k4][m]
        #pragma unroll
        for (int k4 = 0; k4 < 16; k4++) Lreg[k4] = LT4[k4 * 512 + t];
    }
    __syncthreads();

    if (t < 128) {
        int pix = t >> 6, o = t & 63;
        const float* zp = pix ? zpB : zpA;
        float s = (zp[o] + zp[64 + o]) + (zp[128 + o] + zp[192 + o])
                + (zp[256 + o] + zp[320 + o]) + (zp[384 + o] + zp[448 + o]);
        st[pix * 64 + o] = fmaxf(s + b2[o], 0.0f);
    }
    __syncthreads();

    // ============ Phase C: Hopfield retrieve (2 tokens) =====================
    // scores for memory row t (both tokens) from prefetched Lreg; no max
    // subtraction (scores are O(0.3), exp exact-safe; softmax unchanged)
    {
        const float4* st4 = (const float4*)st;
        float a = 0.f, c = 0.f;
        #pragma unroll
        for (int k4 = 0; k4 < 16; k4++) {
            float4 L = Lreg[k4];
            float4 u = st4[k4];
            float4 v = st4[16 + k4];
            a += L.x * u.x + L.y * u.y + L.z * u.z + L.w * u.w;
            c += L.x * v.x + L.y * v.y + L.z * v.z + L.w * v.w;
        }
        ss0[t] = __expf(a * 0.125f);     // 1/sqrt(64)
        ss1[t] = __expf(c * 0.125f);
    }

    // Prefetch p@V's V quads NOW; latency hides behind the sum reduction.
    int g = t >> 4, q = t & 15;
    float4 Vreg[16];
    {
        const float4* V4 = (const float4*)g_V + g * 256 + q;   // m = g*16 + i
        #pragma unroll
        for (int m = 0; m < 16; m++) Vreg[m] = V4[m * 16];
    }

    // block sum (dual)
    float u0 = ss0[t], u1 = ss1[t];
    #pragma unroll
    for (int o = 16; o; o >>= 1) {
        u0 += __shfl_xor_sync(0xffffffffu, u0, o);
        u1 += __shfl_xor_sync(0xffffffffu, u1, o);
    }
    if (lane == 0) { red[warp] = u0; red[16 + warp] = u1; }
    __syncthreads();                 // covers ss writes + red

    // p@V dual from registers: thread (g in 0..31, q in 0..15)
    {
        const float* pp0 = ss0 + g * 16;
        const float* pp1 = ss1 + g * 16;
        float4 A  = make_float4(0.f, 0.f, 0.f, 0.f);
        float4 Bv = make_float4(0.f, 0.f, 0.f, 0.f);
        #pragma unroll
        for (int m = 0; m < 16; m++) {
            float4 v = Vreg[m];
            float pa = pp0[m], pb = pp1[m];
            A.x  += pa * v.x; A.y  += pa * v.y; A.z  += pa * v.z; A.w  += pa * v.w;
            Bv.x += pb * v.x; Bv.y += pb * v.y; Bv.z += pb * v.z; Bv.w += pb * v.w;
        }
        *(float4*)(part + g * 64 + q * 4)        = A;
        *(float4*)(part + 2048 + g * 64 + q * 4) = Bv;
    }

    // totals computed AFTER p@V (only needed at the part-reduce below)
    float tot0 = red[0], tot1 = red[16];
    #pragma unroll
    for (int i = 1; i < 16; i++) { tot0 += red[i]; tot1 += red[16 + i]; }
    float inv0 = __frcp_rn(tot0), inv1 = __frcp_rn(tot1);
    __syncthreads();

    if (t < 128) {
        int j = t >> 6, d = t & 63;
        const float* pp = part + j * 2048;
        float s = 0.f;
        #pragma unroll
        for (int gg = 0; gg < 32; gg += 4)
            s += (pp[gg * 64 + d] + pp[(gg + 1) * 64 + d])
               + (pp[(gg + 2) * 64 + d] + pp[(gg + 3) * 64 + d]);
        pre[j * 64 + d] = s * (j ? inv1 : inv0);
    }
    __syncthreads();

    // @Wo: thread (h4 = t>>7, j = (t>>6)&1, e = t&63); Wo coalesced
    {
        int e = t & 63, j = (t >> 6) & 1, h4 = t >> 7;
        const float* pj = pre + j * 64;
        float acc = 0.f;
        int d0 = h4 * 16;
        #pragma unroll
        for (int d = d0; d < d0 + 16; d++) acc += pj[d] * Wo[d * 64 + e];
        pf[t] = acc;
    }
    __syncthreads();
    if (t < 128) {
        int j = t >> 6, e = t & 63;
        out[b * 4096 + e * 64 + p0 + j] =
            (pf[t] + pf[t + 128]) + (pf[t + 256] + pf[t + 384]);
    }
}

// ---------------------------------------------------------------------------
extern "C" void kernel_launch(void* const* d_in, const int* in_sizes, int n_in,
                              void* d_out, int out_size) {
    const float* x       = (const float*)d_in[0];
    const float* conv1_w = (const float*)d_in[1];
    const float* conv1_b = (const float*)d_in[2];
    const float* conv2_w = (const float*)d_in[3];
    const float* conv2_b = (const float*)d_in[4];
    const float* lookup  = (const float*)d_in[5];
    const float* Wv      = (const float*)d_in[6];
    const float* Wo      = (const float*)d_in[7];
    float* out = (float*)d_out;

    fused_kernel<<<NB, NT>>>(x, conv1_w, conv1_b, conv2_w, conv2_b,
                             lookup, Wv, Wo, out);
}